// round 13
// baseline (speedup 1.0000x reference)
#include <cuda_runtime.h>
#include <cstdint>
#include <math.h>

#define N     16384
#define BKT   8192          // buckets (lambda = 2)
#define NB    16            // CTAs in ONE cluster (non-portable size)
#define TPB   1024          // 16384 threads total -> 1 item per thread
#define HPC   (BKT / NB)    // 512 histogram entries re-zeroed per CTA
#define EPT   (BKT / TPB)   // 8 histogram entries scanned per thread

#define SCALE     16777216.0f            // 2^24 fixed-point for e
#define INV_SCALE 5.9604644775390625e-8f // 2^-24

// ---- global scratch (L2; zero-init at load; re-zeroed each run) ----
// packed entry: (fixed_sum << 20) | count.  Scan-safe: sum_total < 2^44,
// count_total = 16384 < 2^20 (no carry between fields).
__device__ unsigned long long g_H[BKT];
__device__ float2 g_sorted[N];           // {duration, exp(theta)}; overwritten

// dynamic smem: P ull[BKT+1] packed exclusive prefix (64KB + 8)
#define SMEM_BYTES (65536 + 16)
extern __shared__ char smem_raw[];

__device__ __forceinline__ void cluster_sync() {
    // arrive = release, wait = acquire at cluster scope: no explicit fences
    asm volatile("barrier.cluster.arrive.aligned;" ::: "memory");
    asm volatile("barrier.cluster.wait.aligned;" ::: "memory");
}

__device__ __forceinline__ int bucket_of(float d) {
    int b = (int)(d * (float)BKT);
    if (b >= BKT) b = BKT - 1;
    if (b < 0) b = 0;
    return b;
}

__global__ void __launch_bounds__(TPB, 1) __cluster_dims__(NB, 1, 1)
cox_cluster_kernel(const float* __restrict__ theta,
                   const float* __restrict__ dur,
                   const float* __restrict__ ev,
                   float* __restrict__ out) {
    unsigned long long* P = (unsigned long long*)(smem_raw); // excl. prefix

    __shared__ unsigned long long warpTot[32];
    __shared__ unsigned long long warpPre[32];
    __shared__ unsigned long long s_totalP;

    const int t    = threadIdx.x;
    const int k    = blockIdx.x;
    const int g    = k * TPB + t;          // my single item
    const int lane = t & 31;
    const int wid  = t >> 5;

    // ---- Pass A: one packed 64-bit atomic; within-bucket rank from return ----
    float th = theta[g];
    float d  = dur[g];
    float e_ = ev[g];
    float e  = __expf(th);
    int   b  = bucket_of(d);
    unsigned long long pk =
        ((unsigned long long)__float2ull_rn(e * SCALE) << 20) | 1ull;
    unsigned long long old = atomicAdd(&g_H[b], pk);
    int rank = (int)(old & 0xFFFFFull);
    float acc = e_ * th;
    if (g == 0) out[0] = 0.0f;             // ordered before final adds by B1/B2
    cluster_sync();                                            // B1

    // ---- Scan (packed domain): every CTA scans all 8192 entries ----
    // thread t owns contiguous entries [8t, 8t+8)
    unsigned long long h[EPT];
    const int e8 = t * EPT;
    {
        const ulonglong2* H2 = (const ulonglong2*)&g_H[e8];
        #pragma unroll
        for (int j = 0; j < EPT / 2; ++j) {
            ulonglong2 a = __ldcg(&H2[j]);
            h[2*j]   = a.x;
            h[2*j+1] = a.y;
        }
    }
    unsigned long long run = 0ull;
    #pragma unroll
    for (int j = 0; j < EPT; ++j) run += h[j];
    unsigned long long incl = run;
    #pragma unroll
    for (int off = 1; off < 32; off <<= 1) {
        unsigned long long u = __shfl_up_sync(0xFFFFFFFFu, incl, off);
        if (lane >= off) incl += u;
    }
    if (lane == 31) warpTot[wid] = incl;
    __syncthreads();
    if (wid == 0) {
        unsigned long long v = warpTot[lane];
        unsigned long long w = v;
        #pragma unroll
        for (int off = 1; off < 32; off <<= 1) {
            unsigned long long u = __shfl_up_sync(0xFFFFFFFFu, w, off);
            if (lane >= off) w += u;
        }
        warpPre[lane] = w - v;              // exclusive warp prefix
        if (lane == 31) s_totalP = w;       // packed grand total
    }
    __syncthreads();
    unsigned long long ex = warpPre[wid] + (incl - run);
    #pragma unroll
    for (int j = 0; j < EPT; ++j) {
        P[e8 + j] = ex;
        ex += h[j];
    }
    if (t == TPB - 1) P[BKT] = ex;          // sentinel: prefix past last bucket
    const float total = (float)(s_totalP >> 20) * INV_SCALE;
    __syncthreads();

    // ---- Pass B: scatter via prefix count + rank (NO atomics) ----
    const unsigned long long pb = P[b];
    const int s0 = (int)(pb & 0xFFFFFull);  // bucket start
    g_sorted[s0 + rank] = make_float2(d, e);
    cluster_sync();                                            // B2

    // ---- re-zero owned histogram segment (all reads done before B2) ----
    if (t < HPC) g_H[k * HPC + t] = 0ull;

    // ---- Phase 4: per-item risk (prefix from smem, items from L2) ----
    {
        const int s1 = (int)(P[b + 1] & 0xFFFFFull);   // bucket end
        float Sa = (float)(pb >> 20) * INV_SCALE;      // strictly-smaller mass
        int s = s0;
        for (; s + 1 < s1; s += 2) {                   // MLP=2 on the tail
            float2 v0 = __ldcg(&g_sorted[s]);
            float2 v1 = __ldcg(&g_sorted[s + 1]);
            if (v0.x < d) Sa += v0.y;
            if (v1.x < d) Sa += v1.y;
        }
        if (s < s1) {
            float2 v = __ldcg(&g_sorted[s]);
            if (v.x < d) Sa += v.y;          // strict <: self & ties excluded
        }
        float risk = total - Sa;             // sum over d_j >= d_i
        acc -= e_ * __logf(risk);
    }
    #pragma unroll
    for (int off = 16; off > 0; off >>= 1)
        acc += __shfl_down_sync(0xFFFFFFFFu, acc, off);
    if (lane == 0) atomicAdd(out, -acc / (float)N);
    // kernel exit flushes atomics; g_H left zeroed for next replay
}

extern "C" void kernel_launch(void* const* d_in, const int* in_sizes, int n_in,
                              void* d_out, int out_size) {
    const float* theta = (const float*)d_in[0];  // hazard_pred (N,1)
    const float* dur   = (const float*)d_in[1];  // durations (N,)
    const float* ev    = (const float*)d_in[2];  // events (N,)
    float* out = (float*)d_out;

    static int configured = 0;
    if (!configured) {
        cudaFuncSetAttribute(cox_cluster_kernel,
                             cudaFuncAttributeMaxDynamicSharedMemorySize,
                             SMEM_BYTES);
        cudaFuncSetAttribute(cox_cluster_kernel,
                             cudaFuncAttributeNonPortableClusterSizeAllowed, 1);
        configured = 1;
    }
    cox_cluster_kernel<<<NB, TPB, SMEM_BYTES>>>(theta, dur, ev, out);
}

// round 14
// speedup vs baseline: 1.1253x; 1.1253x over previous
#include <cuda_runtime.h>
#include <cstdint>
#include <math.h>

#define N     16384
#define BKT   4096          // buckets (lambda = 4)
#define NB    16            // CTAs in ONE cluster (non-portable size)
#define TPB   1024          // 16384 threads total -> 1 item per thread
#define HPC   (BKT / NB)    // 256 histogram entries re-zeroed per CTA
#define EPT   (BKT / TPB)   // 4 histogram entries scanned per thread

#define SCALE     16777216.0f            // 2^24 fixed-point for e
#define INV_SCALE 5.9604644775390625e-8f // 2^-24

// ---- global scratch (L2; zero-init at load; re-zeroed each run) ----
// packed entry: (fixed_sum << 20) | count.  Scan-safe: sum_total < 2^44,
// count_total = 16384 < 2^20 (no carry between fields).
__device__ unsigned long long g_H[BKT];
__device__ float2 g_sorted[N];           // {duration, exp(theta)}; overwritten

// dynamic smem: P ull[BKT+1] packed exclusive prefix (32KB + 8)
#define SMEM_BYTES (32768 + 16)
extern __shared__ char smem_raw[];

__device__ __forceinline__ void cluster_sync() {
    // arrive = release, wait = acquire at cluster scope: no explicit fences
    asm volatile("barrier.cluster.arrive.aligned;" ::: "memory");
    asm volatile("barrier.cluster.wait.aligned;" ::: "memory");
}

__device__ __forceinline__ int bucket_of(float d) {
    int b = (int)(d * (float)BKT);
    if (b >= BKT) b = BKT - 1;
    if (b < 0) b = 0;
    return b;
}

__global__ void __launch_bounds__(TPB, 1) __cluster_dims__(NB, 1, 1)
cox_cluster_kernel(const float* __restrict__ theta,
                   const float* __restrict__ dur,
                   const float* __restrict__ ev,
                   float* __restrict__ out) {
    unsigned long long* P = (unsigned long long*)(smem_raw); // excl. prefix

    __shared__ unsigned long long warpTot[32];
    __shared__ unsigned long long warpPre[32];
    __shared__ unsigned long long s_totalP;

    const int t    = threadIdx.x;
    const int k    = blockIdx.x;
    const int g    = k * TPB + t;          // my single item
    const int lane = t & 31;
    const int wid  = t >> 5;

    // ---- Pass A: one packed 64-bit atomic; within-bucket rank from return ----
    float th = theta[g];
    float d  = dur[g];
    float e_ = ev[g];
    float e  = __expf(th);
    int   b  = bucket_of(d);
    unsigned long long pk =
        ((unsigned long long)__float2ull_rn(e * SCALE) << 20) | 1ull;
    unsigned long long old = atomicAdd(&g_H[b], pk);
    int rank = (int)(old & 0xFFFFFull);
    float acc = e_ * th;
    if (g == 0) out[0] = 0.0f;             // ordered before final adds by B1/B2
    cluster_sync();                                            // B1

    // ---- Scan (packed domain): every CTA scans all 4096 entries ----
    // thread t owns contiguous entries [4t, 4t+4)
    unsigned long long h[EPT];
    const int e4 = t * EPT;
    {
        const ulonglong2* H2 = (const ulonglong2*)&g_H[e4];
        ulonglong2 a = __ldcg(&H2[0]);
        ulonglong2 c = __ldcg(&H2[1]);
        h[0] = a.x; h[1] = a.y; h[2] = c.x; h[3] = c.y;
    }
    unsigned long long run = h[0] + h[1] + h[2] + h[3];
    unsigned long long incl = run;
    #pragma unroll
    for (int off = 1; off < 32; off <<= 1) {
        unsigned long long u = __shfl_up_sync(0xFFFFFFFFu, incl, off);
        if (lane >= off) incl += u;
    }
    if (lane == 31) warpTot[wid] = incl;
    __syncthreads();
    if (wid == 0) {
        unsigned long long v = warpTot[lane];
        unsigned long long w = v;
        #pragma unroll
        for (int off = 1; off < 32; off <<= 1) {
            unsigned long long u = __shfl_up_sync(0xFFFFFFFFu, w, off);
            if (lane >= off) w += u;
        }
        warpPre[lane] = w - v;              // exclusive warp prefix
        if (lane == 31) s_totalP = w;       // packed grand total
    }
    __syncthreads();
    unsigned long long ex = warpPre[wid] + (incl - run);
    #pragma unroll
    for (int j = 0; j < EPT; ++j) {
        P[e4 + j] = ex;
        ex += h[j];
    }
    if (t == TPB - 1) P[BKT] = ex;          // sentinel: prefix past last bucket
    const float total = (float)(s_totalP >> 20) * INV_SCALE;
    __syncthreads();

    // ---- Pass B: scatter via prefix count + rank (NO atomics) ----
    const unsigned long long pb = P[b];
    const int s0 = (int)(pb & 0xFFFFFull);  // bucket start
    g_sorted[s0 + rank] = make_float2(d, e);
    cluster_sync();                                            // B2

    // ---- Phase 4: per-item risk (prefix from smem, items from L2) ----
    {
        const int s1 = (int)(P[b + 1] & 0xFFFFFull);   // bucket end
        float Sa = (float)(pb >> 20) * INV_SCALE;      // strictly-smaller mass
        int s = s0;
        for (; s + 1 < s1; s += 2) {                   // MLP=2 on the tail
            float2 v0 = __ldcg(&g_sorted[s]);
            float2 v1 = __ldcg(&g_sorted[s + 1]);
            if (v0.x < d) Sa += v0.y;
            if (v1.x < d) Sa += v1.y;
        }
        if (s < s1) {
            float2 v = __ldcg(&g_sorted[s]);
            if (v.x < d) Sa += v.y;          // strict <: self & ties excluded
        }
        float risk = total - Sa;             // sum over d_j >= d_i
        acc -= e_ * __logf(risk);
    }
    #pragma unroll
    for (int off = 16; off > 0; off >>= 1)
        acc += __shfl_down_sync(0xFFFFFFFFu, acc, off);
    if (lane == 0) atomicAdd(out, -acc / (float)N);

    // ---- re-zero owned histogram segment (off critical path; B2 ordered
    //      it after all scan reads, kernel end publishes it for next replay) ----
    if (t < HPC) g_H[k * HPC + t] = 0ull;
}

extern "C" void kernel_launch(void* const* d_in, const int* in_sizes, int n_in,
                              void* d_out, int out_size) {
    const float* theta = (const float*)d_in[0];  // hazard_pred (N,1)
    const float* dur   = (const float*)d_in[1];  // durations (N,)
    const float* ev    = (const float*)d_in[2];  // events (N,)
    float* out = (float*)d_out;

    static int configured = 0;
    if (!configured) {
        cudaFuncSetAttribute(cox_cluster_kernel,
                             cudaFuncAttributeMaxDynamicSharedMemorySize,
                             SMEM_BYTES);
        cudaFuncSetAttribute(cox_cluster_kernel,
                             cudaFuncAttributeNonPortableClusterSizeAllowed, 1);
        configured = 1;
    }
    cox_cluster_kernel<<<NB, TPB, SMEM_BYTES>>>(theta, dur, ev, out);
}